// round 1
// baseline (speedup 1.0000x reference)
#include <cuda_runtime.h>
#include <cuda_bf16.h>

#define B_ROWS 32768
#define C_COLS 1000
#define FDIM   256

#define BM 64
#define BN 64
#define BK 16

// Scratch (allocation-free rule: __device__ globals)
__device__ float g_invf[B_ROWS];
__device__ float g_invp[C_COLS];

// ---------------------------------------------------------------------------
// Kernel 1: per-row inverse L2 norm (F.normalize semantics: x / max(||x||, eps))
// One warp per row of 256 floats.
// ---------------------------------------------------------------------------
__global__ void rownorm_kernel(const float* __restrict__ x, int rows, int isProto) {
    int gwarp = (blockIdx.x * blockDim.x + threadIdx.x) >> 5;
    int lane  = threadIdx.x & 31;
    if (gwarp >= rows) return;
    const float* r = x + (size_t)gwarp * FDIM;
    float s = 0.f;
#pragma unroll
    for (int i = 0; i < FDIM / 32; i++) {
        float v = r[lane + 32 * i];
        s = fmaf(v, v, s);
    }
#pragma unroll
    for (int o = 16; o; o >>= 1) s += __shfl_xor_sync(0xffffffffu, s, o);
    if (lane == 0) {
        float inv = 1.0f / fmaxf(sqrtf(s), 1e-12f);
        if (isProto) g_invp[gwarp] = inv;
        else         g_invf[gwarp] = inv;
    }
}

// ---------------------------------------------------------------------------
// Kernel 2: tiled SGEMM  cos[b,c] = <feat_b, proto_c> * invf[b] * invp[c],
// epilogue writes iso = |ds| * sqrt(max(1-cos, 0)) into out.
// BM=64 x BN=64 tile, BK=16, 256 threads, 4x4 register micro-tile.
// ---------------------------------------------------------------------------
__global__ void __launch_bounds__(256) gemm_iso_kernel(
    const float* __restrict__ A,     // [B_ROWS, FDIM]
    const float* __restrict__ P,     // [C_COLS, FDIM]
    const float* __restrict__ dscale,
    float* __restrict__ out)         // [B_ROWS, C_COLS]
{
    __shared__ float As[BK][BM];
    __shared__ float Bs[BK][BN];

    const int tid  = threadIdx.x;
    const int tx   = tid & 15;   // 0..15 -> column group
    const int ty   = tid >> 4;   // 0..15 -> row group
    const int brow = blockIdx.y * BM;
    const int bcol = blockIdx.x * BN;

    // load mapping: kk = k within tile, mm = base row/col for strided loads
    const int kk = tid & 15;
    const int mm = tid >> 4;

    float acc[4][4] = {};

    for (int k0 = 0; k0 < FDIM; k0 += BK) {
#pragma unroll
        for (int j = 0; j < 4; j++) {
            int m = mm + 16 * j;
            As[kk][m] = A[(size_t)(brow + m) * FDIM + (k0 + kk)];
        }
#pragma unroll
        for (int j = 0; j < 4; j++) {
            int n   = mm + 16 * j;
            int col = bcol + n;
            Bs[kk][n] = (col < C_COLS) ? P[(size_t)col * FDIM + (k0 + kk)] : 0.0f;
        }
        __syncthreads();

#pragma unroll
        for (int k = 0; k < BK; k++) {
            float4 av = *reinterpret_cast<const float4*>(&As[k][ty * 4]);
            float4 bv = *reinterpret_cast<const float4*>(&Bs[k][tx * 4]);
            float a[4] = {av.x, av.y, av.z, av.w};
            float b[4] = {bv.x, bv.y, bv.z, bv.w};
#pragma unroll
            for (int i = 0; i < 4; i++)
#pragma unroll
                for (int j = 0; j < 4; j++)
                    acc[i][j] = fmaf(a[i], b[j], acc[i][j]);
        }
        __syncthreads();
    }

    const float s = fabsf(dscale[0]);
#pragma unroll
    for (int i = 0; i < 4; i++) {
        int   row = brow + ty * 4 + i;
        float fi  = g_invf[row];
#pragma unroll
        for (int j = 0; j < 4; j++) {
            int col = bcol + tx * 4 + j;
            if (col < C_COLS) {
                float c    = acc[i][j] * fi * g_invp[col];
                float dist = sqrtf(fmaxf(1.0f - c, 0.0f));
                out[(size_t)row * C_COLS + col] = s * dist;
            }
        }
    }
}

// ---------------------------------------------------------------------------
// Kernel 3: per-row finalize: logits = -(iso + mean_row(iso)) / temperature
// One block (256 threads) per row.
// ---------------------------------------------------------------------------
__global__ void __launch_bounds__(256) finalize_kernel(
    float* __restrict__ out, const float* __restrict__ temp)
{
    const int row = blockIdx.x;
    float* r = out + (size_t)row * C_COLS;

    float sum = 0.f;
    for (int c = threadIdx.x; c < C_COLS; c += 256) sum += r[c];

    __shared__ float red[8];
#pragma unroll
    for (int o = 16; o; o >>= 1) sum += __shfl_xor_sync(0xffffffffu, sum, o);
    int warp = threadIdx.x >> 5, lane = threadIdx.x & 31;
    if (lane == 0) red[warp] = sum;
    __syncthreads();
    if (warp == 0) {
        float v = (lane < 8) ? red[lane] : 0.0f;
#pragma unroll
        for (int o = 4; o; o >>= 1) v += __shfl_xor_sync(0xffffffffu, v, o);
        if (lane == 0) red[0] = v;
    }
    __syncthreads();

    const float mean = red[0] * (1.0f / (float)C_COLS);
    const float it   = 1.0f / temp[0];
    for (int c = threadIdx.x; c < C_COLS; c += 256)
        r[c] = -(r[c] + mean) * it;
}

// ---------------------------------------------------------------------------
extern "C" void kernel_launch(void* const* d_in, const int* in_sizes, int n_in,
                              void* d_out, int out_size)
{
    const float* feats  = (const float*)d_in[0];  // [32768, 256]
    const float* protos = (const float*)d_in[1];  // [1000, 256]
    const float* ds     = (const float*)d_in[2];  // [1]
    const float* temp   = (const float*)d_in[3];  // [1]
    float* out = (float*)d_out;                   // [32768, 1000]

    // 1) inv norms (8 warps per block)
    rownorm_kernel<<<B_ROWS / 8, 256>>>(feats, B_ROWS, 0);
    rownorm_kernel<<<(C_COLS + 7) / 8, 256>>>(protos, C_COLS, 1);

    // 2) GEMM + iso epilogue
    dim3 grid((C_COLS + BN - 1) / BN, B_ROWS / BM);
    gemm_iso_kernel<<<grid, 256>>>(feats, protos, ds, out);

    // 3) row mean + final logits
    finalize_kernel<<<B_ROWS, 256>>>(out, temp);
}

// round 3
// speedup vs baseline: 4.2297x; 4.2297x over previous
#include <cuda_runtime.h>
#include <cuda_bf16.h>
#include <cstdint>

#define B_ROWS 32768
#define C_COLS 1000
#define C_PAD  1024
#define FDIM   256

#define TM   128        // rows per CTA (owns complete rows)
#define TNC  128        // N-chunk width
#define NCHUNKS (C_PAD / TNC)   // 8

#define APAD   264      // 256 + 8 bf16 padding -> conflict-free ldmatrix
#define ROWB   (APAD * 2)       // 528 bytes per smem row
#define A_BYTES (TM * ROWB)     // 67584
#define B_BYTES (TM * ROWB)     // 67584 (chunk is 128 rows too)
#define STAGE_STRIDE 132        // floats, stage reuses B region (128*132*4 = 67584)
#define RS_OFF  (A_BYTES + B_BYTES)
#define SMEM_TOTAL (RS_OFF + TM * 4)   // + rowsum[128]

// ---- scratch (device globals; no runtime allocation) ----------------------
__device__ __nv_bfloat16 g_fb[B_ROWS * FDIM];   // normalized features, bf16
__device__ __nv_bfloat16 g_pb[C_PAD * FDIM];    // normalized prototypes, bf16 (zero-padded)

// ---- helpers ---------------------------------------------------------------
__device__ __forceinline__ uint32_t smem_u32(const void* p) {
    uint32_t a;
    asm("{ .reg .u64 t; cvta.to.shared.u64 t, %1; cvt.u32.u64 %0, t; }" : "=r"(a) : "l"(p));
    return a;
}
__device__ __forceinline__ void ldsm4(uint32_t* r, uint32_t addr) {
    asm volatile("ldmatrix.sync.aligned.m8n8.x4.shared.b16 {%0,%1,%2,%3}, [%4];"
                 : "=r"(r[0]), "=r"(r[1]), "=r"(r[2]), "=r"(r[3]) : "r"(addr));
}
__device__ __forceinline__ void mma16816(float* c, const uint32_t* a, uint32_t b0, uint32_t b1) {
    asm volatile(
        "mma.sync.aligned.m16n8k16.row.col.f32.bf16.bf16.f32 "
        "{%0,%1,%2,%3}, {%4,%5,%6,%7}, {%8,%9}, {%0,%1,%2,%3};"
        : "+f"(c[0]), "+f"(c[1]), "+f"(c[2]), "+f"(c[3])
        : "r"(a[0]), "r"(a[1]), "r"(a[2]), "r"(a[3]), "r"(b0), "r"(b1));
}

// ---------------------------------------------------------------------------
// Convert + normalize: one warp per row, write 8 bf16 per lane (uint4)
// ---------------------------------------------------------------------------
__global__ void __launch_bounds__(256) conv_feat_kernel(const float* __restrict__ x) {
    int gw   = (blockIdx.x * blockDim.x + threadIdx.x) >> 5;
    int lane = threadIdx.x & 31;
    if (gw >= B_ROWS) return;
    const float4* r4 = reinterpret_cast<const float4*>(x + (size_t)gw * FDIM);
    float4 a = r4[lane * 2], b = r4[lane * 2 + 1];
    float s = a.x*a.x + a.y*a.y + a.z*a.z + a.w*a.w + b.x*b.x + b.y*b.y + b.z*b.z + b.w*b.w;
#pragma unroll
    for (int o = 16; o; o >>= 1) s += __shfl_xor_sync(0xffffffffu, s, o);
    float inv = 1.0f / fmaxf(sqrtf(s), 1e-12f);
    __nv_bfloat162 p0 = __floats2bfloat162_rn(a.x*inv, a.y*inv);
    __nv_bfloat162 p1 = __floats2bfloat162_rn(a.z*inv, a.w*inv);
    __nv_bfloat162 p2 = __floats2bfloat162_rn(b.x*inv, b.y*inv);
    __nv_bfloat162 p3 = __floats2bfloat162_rn(b.z*inv, b.w*inv);
    uint4 o4;
    o4.x = *reinterpret_cast<uint32_t*>(&p0); o4.y = *reinterpret_cast<uint32_t*>(&p1);
    o4.z = *reinterpret_cast<uint32_t*>(&p2); o4.w = *reinterpret_cast<uint32_t*>(&p3);
    reinterpret_cast<uint4*>(g_fb)[(size_t)gw * 32 + lane] = o4;
}

__global__ void __launch_bounds__(256) conv_proto_kernel(const float* __restrict__ x) {
    int gw   = (blockIdx.x * blockDim.x + threadIdx.x) >> 5;
    int lane = threadIdx.x & 31;
    if (gw >= C_PAD) return;
    uint4 o4 = {0u, 0u, 0u, 0u};
    if (gw < C_COLS) {
        const float4* r4 = reinterpret_cast<const float4*>(x + (size_t)gw * FDIM);
        float4 a = r4[lane * 2], b = r4[lane * 2 + 1];
        float s = a.x*a.x + a.y*a.y + a.z*a.z + a.w*a.w + b.x*b.x + b.y*b.y + b.z*b.z + b.w*b.w;
#pragma unroll
        for (int o = 16; o; o >>= 1) s += __shfl_xor_sync(0xffffffffu, s, o);
        float inv = 1.0f / fmaxf(sqrtf(s), 1e-12f);
        __nv_bfloat162 p0 = __floats2bfloat162_rn(a.x*inv, a.y*inv);
        __nv_bfloat162 p1 = __floats2bfloat162_rn(a.z*inv, a.w*inv);
        __nv_bfloat162 p2 = __floats2bfloat162_rn(b.x*inv, b.y*inv);
        __nv_bfloat162 p3 = __floats2bfloat162_rn(b.z*inv, b.w*inv);
        o4.x = *reinterpret_cast<uint32_t*>(&p0); o4.y = *reinterpret_cast<uint32_t*>(&p1);
        o4.z = *reinterpret_cast<uint32_t*>(&p2); o4.w = *reinterpret_cast<uint32_t*>(&p3);
    }
    reinterpret_cast<uint4*>(g_pb)[(size_t)gw * 32 + lane] = o4;
}

// ---------------------------------------------------------------------------
// Fused GEMM + iso + rowmean + logits. One CTA = 128 complete rows.
// 256 threads = 8 warps in a 4(M) x 2(N) grid; warp tile 32x64; mma m16n8k16.
// ---------------------------------------------------------------------------
__global__ void __launch_bounds__(256) fused_kernel(
    const float* __restrict__ dscale,
    const float* __restrict__ temp,
    float* __restrict__ out)
{
    extern __shared__ char smem[];
    char*  smA   = smem;
    char*  smB   = smem + A_BYTES;
    float* stage = reinterpret_cast<float*>(smB);        // reuses B region
    float* rs    = reinterpret_cast<float*>(smem + RS_OFF);

    const uint32_t sbA = smem_u32(smA);
    const uint32_t sbB = smem_u32(smB);

    const int tid  = threadIdx.x;
    const int wid  = tid >> 5;
    const int lane = tid & 31;
    const int wm   = wid & 3;        // 0..3 -> mbase = wm*32
    const int wn   = wid >> 2;       // 0..1 -> nbase = wn*64
    const int row0 = blockIdx.x * TM;

    // zero rowsums
    if (tid < TM) rs[tid] = 0.0f;

    // ---- load A tile (128 x 256 bf16), once ----
    const uint4* fb4 = reinterpret_cast<const uint4*>(g_fb);
    for (int idx = tid; idx < TM * 32; idx += 256) {
        int r = idx >> 5, kc = idx & 31;
        uint4 v = fb4[(size_t)(row0 + r) * 32 + kc];
        *reinterpret_cast<uint4*>(smA + r * ROWB + kc * 16) = v;
    }

    const float s   = fabsf(__ldg(dscale));
    const uint32_t aBase = sbA + (uint32_t)((wm * 32 + (lane & 15)) * APAD + ((lane >> 4) << 3)) * 2;
    const uint32_t bBase = sbB + (uint32_t)((wn * 64 + (lane & 15)) * APAD + ((lane >> 4) << 3)) * 2;

    const uint4* pb4 = reinterpret_cast<const uint4*>(g_pb);

    for (int nc = 0; nc < NCHUNKS; nc++) {
        __syncthreads();   // B/stage region free

        // ---- load B chunk (128 x 256 bf16) ----
        for (int idx = tid; idx < TNC * 32; idx += 256) {
            int r = idx >> 5, kc = idx & 31;
            uint4 v = pb4[(size_t)(nc * TNC + r) * 32 + kc];
            *reinterpret_cast<uint4*>(smB + r * ROWB + kc * 16) = v;
        }
        __syncthreads();

        // ---- MMA mainloop: warp tile 32x64, K=256 ----
        float acc[2][8][4];
#pragma unroll
        for (int i = 0; i < 2; i++)
#pragma unroll
            for (int j = 0; j < 8; j++)
#pragma unroll
                for (int q = 0; q < 4; q++) acc[i][j][q] = 0.0f;

#pragma unroll
        for (int k0 = 0; k0 < FDIM; k0 += 16) {
            uint32_t a0[4], a1[4];
            ldsm4(a0, aBase + k0 * 2);
            ldsm4(a1, aBase + 16 * ROWB + k0 * 2);
            uint32_t b[4][4];
#pragma unroll
            for (int jj = 0; jj < 4; jj++)
                ldsm4(b[jj], bBase + jj * 16 * ROWB + k0 * 2);
#pragma unroll
            for (int j = 0; j < 8; j++) {
                int jj = j >> 1, o = j & 1;
                uint32_t b0 = b[jj][o], b1 = b[jj][o + 2];
                mma16816(acc[0][j], a0, b0, b1);
                mma16816(acc[1][j], a1, b0, b1);
            }
        }
        __syncthreads();   // all MMA done before stage overwrites B

        // ---- stage iso ----
        {
            int q  = lane >> 2;
            int c2 = (lane & 3) * 2;
#pragma unroll
            for (int i = 0; i < 2; i++) {
                int r0 = wm * 32 + 16 * i + q;
#pragma unroll
                for (int j = 0; j < 8; j++) {
                    int cl = wn * 64 + 8 * j + c2;
                    stage[r0 * STAGE_STRIDE + cl]           = s * sqrtf(fmaxf(1.0f - acc[i][j][0], 0.0f));
                    stage[r0 * STAGE_STRIDE + cl + 1]       = s * sqrtf(fmaxf(1.0f - acc[i][j][1], 0.0f));
                    stage[(r0 + 8) * STAGE_STRIDE + cl]     = s * sqrtf(fmaxf(1.0f - acc[i][j][2], 0.0f));
                    stage[(r0 + 8) * STAGE_STRIDE + cl + 1] = s * sqrtf(fmaxf(1.0f - acc[i][j][3], 0.0f));
                }
            }
        }
        __syncthreads();

        // ---- coalesced store + rowsum (warp-uniform row per iteration) ----
#pragma unroll
        for (int it = 0; it < 16; it++) {
            int idx  = tid + it * 256;
            int r    = idx >> 5;
            int c4   = idx & 31;
            int gcol = nc * TNC + c4 * 4;
            float sv = 0.0f;
            if (gcol < C_COLS) {
                float4 v = *reinterpret_cast<const float4*>(&stage[r * STAGE_STRIDE + c4 * 4]);
                *reinterpret_cast<float4*>(&out[(size_t)(row0 + r) * C_COLS + gcol]) = v;
                sv = v.x + v.y + v.z + v.w;
            }
#pragma unroll
            for (int o = 16; o; o >>= 1) sv += __shfl_xor_sync(0xffffffffu, sv, o);
            if (lane == 0) atomicAdd(&rs[r], sv);
        }
    }
    __syncthreads();   // rowsums complete

    // ---- finalize: logits = -(iso + mean) / T  (reread own tile from L2) ----
    const float itT = 1.0f / __ldg(temp);
    for (int idx = tid; idx < TM * (C_COLS / 4); idx += 256) {
        int r = idx / (C_COLS / 4);
        int c = idx - r * (C_COLS / 4);
        float  mean = rs[r] * (1.0f / (float)C_COLS);
        float4* p = reinterpret_cast<float4*>(&out[(size_t)(row0 + r) * C_COLS]) + c;
        float4 v  = __ldcg(p);
        v.x = -(v.x + mean) * itT;
        v.y = -(v.y + mean) * itT;
        v.z = -(v.z + mean) * itT;
        v.w = -(v.w + mean) * itT;
        *p = v;
    }
}

// ---------------------------------------------------------------------------
extern "C" void kernel_launch(void* const* d_in, const int* in_sizes, int n_in,
                              void* d_out, int out_size)
{
    const float* feats  = (const float*)d_in[0];
    const float* protos = (const float*)d_in[1];
    const float* ds     = (const float*)d_in[2];
    const float* temp   = (const float*)d_in[3];
    float* out = (float*)d_out;

    cudaFuncSetAttribute(fused_kernel,
                         cudaFuncAttributeMaxDynamicSharedMemorySize, SMEM_TOTAL);

    conv_feat_kernel<<<B_ROWS / 8, 256>>>(feats);
    conv_proto_kernel<<<C_PAD / 8, 256>>>(protos);
    fused_kernel<<<B_ROWS / TM, 256, SMEM_TOTAL>>>(ds, temp, out);
}

// round 5
// speedup vs baseline: 5.1423x; 1.2158x over previous
#include <cuda_runtime.h>
#include <cuda_bf16.h>
#include <cstdint>

#define B_ROWS 32768
#define C_COLS 1000
#define C_PAD  1024
#define FDIM   256

#define TM   128               // rows per CTA (owns complete rows)
#define TNC  64                // N-chunk width
#define NCHUNKS (C_PAD / TNC)  // 16

#define APAD   264             // 256 + 8 bf16 pad -> conflict-free ldmatrix
#define ROWB   (APAD * 2)      // 528 bytes per smem row
#define A_BYTES (TM * ROWB)    // 67584
#define B_BYTES (TNC * ROWB)   // 33792
#define STAGE_STRIDE 68        // floats; 272B row stride = 17*16B (16B-aligned!)
#define STAGE_BYTES  (TM * STAGE_STRIDE * 4)   // 34816
#define OVR_BYTES    (STAGE_BYTES > B_BYTES ? STAGE_BYTES : B_BYTES)  // 34816
#define RS_OFF  (A_BYTES + OVR_BYTES)    // 102400
#define SMEM_TOTAL (RS_OFF + TM * 4)     // 102912 -> still 2 CTAs/SM

// ---- scratch (device global; no runtime allocation) ------------------------
__device__ __nv_bfloat16 g_pb[C_PAD * FDIM];   // normalized prototypes, bf16 (zero-padded)

// ---- helpers ----------------------------------------------------------------
__device__ __forceinline__ uint32_t smem_u32(const void* p) {
    uint32_t a;
    asm("{ .reg .u64 t; cvta.to.shared.u64 t, %1; cvt.u32.u64 %0, t; }" : "=r"(a) : "l"(p));
    return a;
}
__device__ __forceinline__ void ldsm4(uint32_t* r, uint32_t addr) {
    asm volatile("ldmatrix.sync.aligned.m8n8.x4.shared.b16 {%0,%1,%2,%3}, [%4];"
                 : "=r"(r[0]), "=r"(r[1]), "=r"(r[2]), "=r"(r[3]) : "r"(addr));
}
__device__ __forceinline__ void mma16816(float* c, const uint32_t* a, uint32_t b0, uint32_t b1) {
    asm volatile(
        "mma.sync.aligned.m16n8k16.row.col.f32.bf16.bf16.f32 "
        "{%0,%1,%2,%3}, {%4,%5,%6,%7}, {%8,%9}, {%0,%1,%2,%3};"
        : "+f"(c[0]), "+f"(c[1]), "+f"(c[2]), "+f"(c[3])
        : "r"(a[0]), "r"(a[1]), "r"(a[2]), "r"(a[3]), "r"(b0), "r"(b1));
}

// ---------------------------------------------------------------------------
// Prototype normalize + bf16 convert (1024 padded rows, zero tail).
// ---------------------------------------------------------------------------
__global__ void __launch_bounds__(256) conv_proto_kernel(const float* __restrict__ x) {
    int gw   = (blockIdx.x * blockDim.x + threadIdx.x) >> 5;
    int lane = threadIdx.x & 31;
    if (gw >= C_PAD) return;
    uint4 o4 = {0u, 0u, 0u, 0u};
    if (gw < C_COLS) {
        const float4* r4 = reinterpret_cast<const float4*>(x + (size_t)gw * FDIM);
        float4 a = r4[lane * 2], b = r4[lane * 2 + 1];
        float s = a.x*a.x + a.y*a.y + a.z*a.z + a.w*a.w + b.x*b.x + b.y*b.y + b.z*b.z + b.w*b.w;
#pragma unroll
        for (int o = 16; o; o >>= 1) s += __shfl_xor_sync(0xffffffffu, s, o);
        float inv = 1.0f / fmaxf(sqrtf(s), 1e-12f);
        __nv_bfloat162 p0 = __floats2bfloat162_rn(a.x*inv, a.y*inv);
        __nv_bfloat162 p1 = __floats2bfloat162_rn(a.z*inv, a.w*inv);
        __nv_bfloat162 p2 = __floats2bfloat162_rn(b.x*inv, b.y*inv);
        __nv_bfloat162 p3 = __floats2bfloat162_rn(b.z*inv, b.w*inv);
        o4.x = *reinterpret_cast<uint32_t*>(&p0); o4.y = *reinterpret_cast<uint32_t*>(&p1);
        o4.z = *reinterpret_cast<uint32_t*>(&p2); o4.w = *reinterpret_cast<uint32_t*>(&p3);
    }
    reinterpret_cast<uint4*>(g_pb)[(size_t)gw * 32 + lane] = o4;
}

// ---------------------------------------------------------------------------
// Fused: feature normalize -> bf16 GEMM (HMMA) -> iso -> rowmean -> logits.
// One CTA = 128 complete rows; 8 warps in a 4(M) x 2(N) grid; warp tile 32x32.
// ---------------------------------------------------------------------------
__global__ void __launch_bounds__(256, 2) fused_kernel(
    const float* __restrict__ feats,
    const float* __restrict__ dscale,
    const float* __restrict__ temp,
    float* __restrict__ out)
{
    extern __shared__ char smem[];
    char*  smA   = smem;
    char*  smB   = smem + A_BYTES;
    float* stage = reinterpret_cast<float*>(smB);        // overlays B region
    float* rs    = reinterpret_cast<float*>(smem + RS_OFF);

    const uint32_t sbA = smem_u32(smA);
    const uint32_t sbB = smem_u32(smB);

    const int tid  = threadIdx.x;
    const int wid  = tid >> 5;
    const int lane = tid & 31;
    const int wm   = wid & 3;        // M warp: rows wm*32
    const int wn   = wid >> 2;       // N warp: cols wn*32
    const int row0 = blockIdx.x * TM;

    if (tid < TM) rs[tid] = 0.0f;

    // ---- A tile: load fp32, normalize, convert, store bf16 (warp per row) ----
    const float4* f4 = reinterpret_cast<const float4*>(feats);
#pragma unroll
    for (int rr = 0; rr < TM / 8; rr++) {
        int r = wid + rr * 8;
        float4 a = f4[(size_t)(row0 + r) * 64 + lane * 2];
        float4 b = f4[(size_t)(row0 + r) * 64 + lane * 2 + 1];
        float s = a.x*a.x + a.y*a.y + a.z*a.z + a.w*a.w + b.x*b.x + b.y*b.y + b.z*b.z + b.w*b.w;
#pragma unroll
        for (int o = 16; o; o >>= 1) s += __shfl_xor_sync(0xffffffffu, s, o);
        float inv = 1.0f / fmaxf(sqrtf(s), 1e-12f);
        __nv_bfloat162 p0 = __floats2bfloat162_rn(a.x*inv, a.y*inv);
        __nv_bfloat162 p1 = __floats2bfloat162_rn(a.z*inv, a.w*inv);
        __nv_bfloat162 p2 = __floats2bfloat162_rn(b.x*inv, b.y*inv);
        __nv_bfloat162 p3 = __floats2bfloat162_rn(b.z*inv, b.w*inv);
        uint4 o4;
        o4.x = *reinterpret_cast<uint32_t*>(&p0); o4.y = *reinterpret_cast<uint32_t*>(&p1);
        o4.z = *reinterpret_cast<uint32_t*>(&p2); o4.w = *reinterpret_cast<uint32_t*>(&p3);
        *reinterpret_cast<uint4*>(smA + r * ROWB + lane * 16) = o4;
    }

    const float s = fabsf(__ldg(dscale));
    const uint32_t aBase = sbA + (uint32_t)((wm * 32 + (lane & 15)) * APAD + ((lane >> 4) << 3)) * 2;
    const uint32_t bBase = sbB + (uint32_t)((wn * 32 + (lane & 15)) * APAD + ((lane >> 4) << 3)) * 2;

    const uint4* pb4 = reinterpret_cast<const uint4*>(g_pb);

    for (int nc = 0; nc < NCHUNKS; nc++) {
        __syncthreads();   // B/stage region free (also covers first A-tile use)

        // ---- load B chunk (64 x 256 bf16): 2048 uint4 / 256 thr = 8 iters ----
#pragma unroll
        for (int i = 0; i < 8; i++) {
            int idx = tid + i * 256;
            int r = idx >> 5, kc = idx & 31;
            uint4 v = pb4[(size_t)(nc * TNC + r) * 32 + kc];
            *reinterpret_cast<uint4*>(smB + r * ROWB + kc * 16) = v;
        }
        __syncthreads();

        // ---- MMA mainloop: warp tile 32x32, K=256 ----
        float acc[2][4][4];
#pragma unroll
        for (int i = 0; i < 2; i++)
#pragma unroll
            for (int j = 0; j < 4; j++)
#pragma unroll
                for (int q = 0; q < 4; q++) acc[i][j][q] = 0.0f;

#pragma unroll
        for (int k0 = 0; k0 < FDIM; k0 += 16) {
            uint32_t a0[4], a1[4];
            ldsm4(a0, aBase + k0 * 2);
            ldsm4(a1, aBase + 16 * ROWB + k0 * 2);
            uint32_t b[2][4];
            ldsm4(b[0], bBase + k0 * 2);
            ldsm4(b[1], bBase + 16 * ROWB + k0 * 2);
#pragma unroll
            for (int j = 0; j < 4; j++) {
                int jj = j >> 1, o = j & 1;
                uint32_t b0 = b[jj][o], b1 = b[jj][o + 2];
                mma16816(acc[0][j], a0, b0, b1);
                mma16816(acc[1][j], a1, b0, b1);
            }
        }
        __syncthreads();   // MMA reads done before stage overwrites B

        // ---- stage iso into SMEM ----
        {
            int q  = lane >> 2;
            int c2 = (lane & 3) * 2;
#pragma unroll
            for (int i = 0; i < 2; i++) {
                int r0 = wm * 32 + 16 * i + q;
#pragma unroll
                for (int j = 0; j < 4; j++) {
                    int cl = wn * 32 + 8 * j + c2;
                    stage[r0 * STAGE_STRIDE + cl]           = s * sqrtf(fmaxf(1.0f - acc[i][j][0], 0.0f));
                    stage[r0 * STAGE_STRIDE + cl + 1]       = s * sqrtf(fmaxf(1.0f - acc[i][j][1], 0.0f));
                    stage[(r0 + 8) * STAGE_STRIDE + cl]     = s * sqrtf(fmaxf(1.0f - acc[i][j][2], 0.0f));
                    stage[(r0 + 8) * STAGE_STRIDE + cl + 1] = s * sqrtf(fmaxf(1.0f - acc[i][j][3], 0.0f));
                }
            }
        }
        __syncthreads();

        // ---- coalesced store + rowsum: 128 rows x 16 float4 = 8 iters ----
#pragma unroll
        for (int it = 0; it < 8; it++) {
            int idx  = tid + it * 256;
            int r    = idx >> 4;               // warp spans 2 rows
            int c4   = idx & 15;
            int gcol = nc * TNC + c4 * 4;
            float sv = 0.0f;
            if (gcol < C_COLS) {
                float4 v = *reinterpret_cast<const float4*>(&stage[r * STAGE_STRIDE + c4 * 4]);
                *reinterpret_cast<float4*>(&out[(size_t)(row0 + r) * C_COLS + gcol]) = v;
                sv = v.x + v.y + v.z + v.w;
            }
#pragma unroll
            for (int o = 8; o; o >>= 1) sv += __shfl_xor_sync(0xffffffffu, sv, o);
            if ((lane & 15) == 0) atomicAdd(&rs[r], sv);
        }
    }
    __syncthreads();   // rowsums complete

    // ---- finalize: logits = -(iso + mean)/T  (reread own tile, L2-hot) ----
    const float itT = 1.0f / __ldg(temp);
    for (int idx = tid; idx < TM * (C_COLS / 4); idx += 256) {
        int r = idx / (C_COLS / 4);
        int c = idx - r * (C_COLS / 4);
        float  mean = rs[r] * (1.0f / (float)C_COLS);
        float4* p = reinterpret_cast<float4*>(&out[(size_t)(row0 + r) * C_COLS]) + c;
        float4 v  = __ldcg(p);
        v.x = -(v.x + mean) * itT;
        v.y = -(v.y + mean) * itT;
        v.z = -(v.z + mean) * itT;
        v.w = -(v.w + mean) * itT;
        *p = v;
    }
}

// ---------------------------------------------------------------------------
extern "C" void kernel_launch(void* const* d_in, const int* in_sizes, int n_in,
                              void* d_out, int out_size)
{
    const float* feats  = (const float*)d_in[0];
    const float* protos = (const float*)d_in[1];
    const float* ds     = (const float*)d_in[2];
    const float* temp   = (const float*)d_in[3];
    float* out = (float*)d_out;

    cudaFuncSetAttribute(fused_kernel,
                         cudaFuncAttributeMaxDynamicSharedMemorySize, SMEM_TOTAL);

    conv_proto_kernel<<<C_PAD / 8, 256>>>(protos);
    fused_kernel<<<B_ROWS / TM, 256, SMEM_TOTAL>>>(feats, ds, temp, out);
}

// round 6
// speedup vs baseline: 5.6426x; 1.0973x over previous
#include <cuda_runtime.h>
#include <cuda_bf16.h>
#include <cstdint>

#define B_ROWS 32768
#define C_COLS 1000
#define C_PAD  1024
#define FDIM   256

#define TM   128               // rows per CTA
#define TNC  32                // N-chunk width
#define NCHUNKS (C_PAD / TNC)  // 32

#define APAD   264             // 256 + 8 bf16 pad -> conflict-free ldmatrix
#define ROWB   (APAD * 2)      // 528 B per smem row
#define A_BYTES (TM * ROWB)    // 67584
#define B_BUF   (TNC * ROWB)   // 16896 per buffer
#define RS_OFF  (A_BYTES + 2 * B_BUF)    // 101376
#define SMEM_TOTAL (RS_OFF + TM * 4)     // 101888 -> 2 CTAs/SM

// ---- scratch (device global; no runtime allocation) ------------------------
__device__ __nv_bfloat16 g_pb[C_PAD * FDIM];   // normalized prototypes, bf16 (zero-padded)

// ---- helpers ----------------------------------------------------------------
__device__ __forceinline__ uint32_t smem_u32(const void* p) {
    uint32_t a;
    asm("{ .reg .u64 t; cvta.to.shared.u64 t, %1; cvt.u32.u64 %0, t; }" : "=r"(a) : "l"(p));
    return a;
}
__device__ __forceinline__ void ldsm4(uint32_t* r, uint32_t addr) {
    asm volatile("ldmatrix.sync.aligned.m8n8.x4.shared.b16 {%0,%1,%2,%3}, [%4];"
                 : "=r"(r[0]), "=r"(r[1]), "=r"(r[2]), "=r"(r[3]) : "r"(addr));
}
__device__ __forceinline__ void mma16816(float* c, const uint32_t* a, uint32_t b0, uint32_t b1) {
    asm volatile(
        "mma.sync.aligned.m16n8k16.row.col.f32.bf16.bf16.f32 "
        "{%0,%1,%2,%3}, {%4,%5,%6,%7}, {%8,%9}, {%0,%1,%2,%3};"
        : "+f"(c[0]), "+f"(c[1]), "+f"(c[2]), "+f"(c[3])
        : "r"(a[0]), "r"(a[1]), "r"(a[2]), "r"(a[3]), "r"(b0), "r"(b1));
}
__device__ __forceinline__ void cp_async16(uint32_t smem_dst, const void* gptr) {
    asm volatile("cp.async.cg.shared.global [%0], [%1], 16;"
                 :: "r"(smem_dst), "l"(gptr) : "memory");
}
__device__ __forceinline__ void cp_commit() {
    asm volatile("cp.async.commit_group;" ::: "memory");
}
__device__ __forceinline__ void cp_wait1() {
    asm volatile("cp.async.wait_group 1;" ::: "memory");
}

// ---------------------------------------------------------------------------
// Prototype normalize + bf16 convert (1024 padded rows, zero tail).
// ---------------------------------------------------------------------------
__global__ void __launch_bounds__(256) conv_proto_kernel(const float* __restrict__ x) {
    int gw   = (blockIdx.x * blockDim.x + threadIdx.x) >> 5;
    int lane = threadIdx.x & 31;
    if (gw >= C_PAD) return;
    uint4 o4 = {0u, 0u, 0u, 0u};
    if (gw < C_COLS) {
        const float4* r4 = reinterpret_cast<const float4*>(x + (size_t)gw * FDIM);
        float4 a = r4[lane * 2], b = r4[lane * 2 + 1];
        float s = a.x*a.x + a.y*a.y + a.z*a.z + a.w*a.w + b.x*b.x + b.y*b.y + b.z*b.z + b.w*b.w;
#pragma unroll
        for (int o = 16; o; o >>= 1) s += __shfl_xor_sync(0xffffffffu, s, o);
        float inv = 1.0f / fmaxf(sqrtf(s), 1e-12f);
        __nv_bfloat162 p0 = __floats2bfloat162_rn(a.x*inv, a.y*inv);
        __nv_bfloat162 p1 = __floats2bfloat162_rn(a.z*inv, a.w*inv);
        __nv_bfloat162 p2 = __floats2bfloat162_rn(b.x*inv, b.y*inv);
        __nv_bfloat162 p3 = __floats2bfloat162_rn(b.z*inv, b.w*inv);
        o4.x = *reinterpret_cast<uint32_t*>(&p0); o4.y = *reinterpret_cast<uint32_t*>(&p1);
        o4.z = *reinterpret_cast<uint32_t*>(&p2); o4.w = *reinterpret_cast<uint32_t*>(&p3);
    }
    reinterpret_cast<uint4*>(g_pb)[(size_t)gw * 32 + lane] = o4;
}

// ---------------------------------------------------------------------------
// Fused: normalize -> bf16 HMMA GEMM (cp.async pipelined) -> iso -> mean -> logits
// 8 warps: 4(M) x 2(N); warp tile 32x16; double-buffered B chunks of 32 cols.
// ---------------------------------------------------------------------------
__global__ void __launch_bounds__(256, 2) fused_kernel(
    const float* __restrict__ feats,
    const float* __restrict__ dscale,
    const float* __restrict__ temp,
    float* __restrict__ out)
{
    extern __shared__ char smem[];
    char*  smA = smem;
    char*  smB = smem + A_BYTES;
    float* rs  = reinterpret_cast<float*>(smem + RS_OFF);

    const uint32_t sbA  = smem_u32(smA);
    const uint32_t sbB  = smem_u32(smB);

    const int tid  = threadIdx.x;
    const int wid  = tid >> 5;
    const int lane = tid & 31;
    const int wm   = wid & 3;        // M warp: rows wm*32
    const int wn   = wid >> 2;       // N warp: cols wn*16
    const int row0 = blockIdx.x * TM;

    if (tid < TM) rs[tid] = 0.0f;

    // ---- A tile: load fp32, normalize, convert, store bf16 (warp per row) ----
    const float4* f4 = reinterpret_cast<const float4*>(feats);
#pragma unroll
    for (int rr = 0; rr < TM / 8; rr++) {
        int r = wid + rr * 8;
        float4 a = f4[(size_t)(row0 + r) * 64 + lane * 2];
        float4 b = f4[(size_t)(row0 + r) * 64 + lane * 2 + 1];
        float s = a.x*a.x + a.y*a.y + a.z*a.z + a.w*a.w + b.x*b.x + b.y*b.y + b.z*b.z + b.w*b.w;
#pragma unroll
        for (int o = 16; o; o >>= 1) s += __shfl_xor_sync(0xffffffffu, s, o);
        float inv = 1.0f / fmaxf(sqrtf(s), 1e-12f);
        __nv_bfloat162 p0 = __floats2bfloat162_rn(a.x*inv, a.y*inv);
        __nv_bfloat162 p1 = __floats2bfloat162_rn(a.z*inv, a.w*inv);
        __nv_bfloat162 p2 = __floats2bfloat162_rn(b.x*inv, b.y*inv);
        __nv_bfloat162 p3 = __floats2bfloat162_rn(b.z*inv, b.w*inv);
        uint4 o4;
        o4.x = *reinterpret_cast<uint32_t*>(&p0); o4.y = *reinterpret_cast<uint32_t*>(&p1);
        o4.z = *reinterpret_cast<uint32_t*>(&p2); o4.w = *reinterpret_cast<uint32_t*>(&p3);
        *reinterpret_cast<uint4*>(smA + r * ROWB + lane * 16) = o4;
    }

    // ---- B chunk loader: 32 rows x 32 16B-chunks = 4 cp.async per thread ----
    const char* pbB = reinterpret_cast<const char*>(g_pb);
    auto load_chunk = [&](int nc, int buf) {
#pragma unroll
        for (int i = 0; i < 4; i++) {
            int idx = tid + i * 256;
            int r = idx >> 5, kc = idx & 31;
            cp_async16(sbB + buf * B_BUF + r * ROWB + kc * 16,
                       pbB + ((size_t)(nc * TNC + r) * FDIM + kc * 8) * 2);
        }
        cp_commit();
    };

    // prologue: prefetch chunks 0 and 1
    load_chunk(0, 0);
    load_chunk(1, 1);

    const float s = fabsf(__ldg(dscale));
    const uint32_t aBase = sbA + (uint32_t)((wm * 32 + (lane & 15)) * APAD + ((lane >> 4) << 3)) * 2;
    const uint32_t bOff  = (uint32_t)((wn * 16 + (lane & 15)) * APAD + ((lane >> 4) << 3)) * 2;
    const int q = lane >> 2;

    float rsum[4] = {0.f, 0.f, 0.f, 0.f};

    for (int nc = 0; nc < NCHUNKS; nc++) {
        cp_wait1();          // chunk nc landed
        __syncthreads();     // visible to all warps (also orders A-tile on nc==0)

        const uint32_t bBase = sbB + (nc & 1) * B_BUF + bOff;

        float acc[2][2][4];
#pragma unroll
        for (int i = 0; i < 2; i++)
#pragma unroll
            for (int j = 0; j < 2; j++)
#pragma unroll
                for (int c = 0; c < 4; c++) acc[i][j][c] = 0.0f;

#pragma unroll
        for (int k0 = 0; k0 < FDIM; k0 += 16) {
            uint32_t a0[4], a1[4], b[4];
            ldsm4(a0, aBase + k0 * 2);
            ldsm4(a1, aBase + 16 * ROWB + k0 * 2);
            ldsm4(b,  bBase + k0 * 2);
            mma16816(acc[0][0], a0, b[0], b[2]);
            mma16816(acc[0][1], a0, b[1], b[3]);
            mma16816(acc[1][0], a1, b[0], b[2]);
            mma16816(acc[1][1], a1, b[1], b[3]);
        }
        __syncthreads();     // all MMA reads of buf[nc&1] done before refill

        if (nc + 2 < NCHUNKS) load_chunk(nc + 2, nc & 1);
        else                  cp_commit();   // keep group count invariant

        // ---- epilogue: iso from fragments, direct float2 stores + reg rowsum ----
        const int cbase = nc * TNC + wn * 16 + (lane & 3) * 2;
#pragma unroll
        for (int i = 0; i < 2; i++) {
            int r0 = row0 + wm * 32 + 16 * i + q;
#pragma unroll
            for (int j = 0; j < 2; j++) {
                int col = cbase + 8 * j;
                if (col < C_COLS) {
                    float i0 = s * sqrtf(fmaxf(1.0f - acc[i][j][0], 0.0f));
                    float i1 = s * sqrtf(fmaxf(1.0f - acc[i][j][1], 0.0f));
                    float i2 = s * sqrtf(fmaxf(1.0f - acc[i][j][2], 0.0f));
                    float i3 = s * sqrtf(fmaxf(1.0f - acc[i][j][3], 0.0f));
                    *reinterpret_cast<float2*>(&out[(size_t)r0 * C_COLS + col])       = make_float2(i0, i1);
                    *reinterpret_cast<float2*>(&out[(size_t)(r0 + 8) * C_COLS + col]) = make_float2(i2, i3);
                    rsum[2 * i]     += i0 + i1;
                    rsum[2 * i + 1] += i2 + i3;
                }
            }
        }
    }

    // ---- rowsum: reduce over the 4 lanes sharing each row, one atomic/row ----
#pragma unroll
    for (int k = 0; k < 4; k++) {
        float v = rsum[k];
        v += __shfl_xor_sync(0xffffffffu, v, 1);
        v += __shfl_xor_sync(0xffffffffu, v, 2);
        if ((lane & 3) == 0) {
            int row = wm * 32 + 16 * (k >> 1) + 8 * (k & 1) + q;
            atomicAdd(&rs[row], v);
        }
    }
    __syncthreads();

    // ---- finalize: logits = -(iso + mean)/T  (reread own tile, L2-hot) ----
    const float itT = 1.0f / __ldg(temp);
    for (int idx = tid; idx < TM * (C_COLS / 4); idx += 256) {
        int r = idx / (C_COLS / 4);
        int c = idx - r * (C_COLS / 4);
        float  mean = rs[r] * (1.0f / (float)C_COLS);
        float4* p = reinterpret_cast<float4*>(&out[(size_t)(row0 + r) * C_COLS]) + c;
        float4 v  = __ldcg(p);
        v.x = -(v.x + mean) * itT;
        v.y = -(v.y + mean) * itT;
        v.z = -(v.z + mean) * itT;
        v.w = -(v.w + mean) * itT;
        *p = v;
    }
}

// ---------------------------------------------------------------------------
extern "C" void kernel_launch(void* const* d_in, const int* in_sizes, int n_in,
                              void* d_out, int out_size)
{
    const float* feats  = (const float*)d_in[0];
    const float* protos = (const float*)d_in[1];
    const float* ds     = (const float*)d_in[2];
    const float* temp   = (const float*)d_in[3];
    float* out = (float*)d_out;

    cudaFuncSetAttribute(fused_kernel,
                         cudaFuncAttributeMaxDynamicSharedMemorySize, SMEM_TOTAL);

    conv_proto_kernel<<<C_PAD / 8, 256>>>(protos);
    fused_kernel<<<B_ROWS / TM, 256, SMEM_TOTAL>>>(feats, ds, temp, out);
}

// round 7
// speedup vs baseline: 5.7810x; 1.0245x over previous
#include <cuda_runtime.h>
#include <cuda_bf16.h>
#include <cstdint>

#define B_ROWS 32768
#define C_COLS 1000
#define C_PAD  1024
#define FDIM   256

#define TM   32                // rows per CTA (cos tile fully register-resident)
#define TNC  128               // N-chunk width
#define NCHUNKS (C_PAD / TNC)  // 8

#define APAD   264             // 256 + 8 bf16 pad -> conflict-free ldmatrix
#define ROWB   (APAD * 2)      // 528 B per smem row
#define A_BYTES (TM * ROWB)    // 16896
#define B_BUF   (TNC * ROWB)   // 67584 per buffer
#define RS_OFF  (A_BYTES + 2 * B_BUF)    // 152064
#define SMEM_TOTAL (RS_OFF + TM * 4)     // 152192 (1 CTA/SM)

// ---- scratch (device global; no runtime allocation) ------------------------
__device__ __nv_bfloat16 g_pb[C_PAD * FDIM];   // normalized prototypes, bf16 (zero-padded)

// ---- helpers ----------------------------------------------------------------
__device__ __forceinline__ uint32_t smem_u32(const void* p) {
    uint32_t a;
    asm("{ .reg .u64 t; cvta.to.shared.u64 t, %1; cvt.u32.u64 %0, t; }" : "=r"(a) : "l"(p));
    return a;
}
__device__ __forceinline__ void ldsm4(uint32_t* r, uint32_t addr) {
    asm volatile("ldmatrix.sync.aligned.m8n8.x4.shared.b16 {%0,%1,%2,%3}, [%4];"
                 : "=r"(r[0]), "=r"(r[1]), "=r"(r[2]), "=r"(r[3]) : "r"(addr));
}
__device__ __forceinline__ void mma16816(float* c, const uint32_t* a, uint32_t b0, uint32_t b1) {
    asm volatile(
        "mma.sync.aligned.m16n8k16.row.col.f32.bf16.bf16.f32 "
        "{%0,%1,%2,%3}, {%4,%5,%6,%7}, {%8,%9}, {%0,%1,%2,%3};"
        : "+f"(c[0]), "+f"(c[1]), "+f"(c[2]), "+f"(c[3])
        : "r"(a[0]), "r"(a[1]), "r"(a[2]), "r"(a[3]), "r"(b0), "r"(b1));
}
__device__ __forceinline__ void cp_async16(uint32_t smem_dst, const void* gptr) {
    asm volatile("cp.async.cg.shared.global [%0], [%1], 16;"
                 :: "r"(smem_dst), "l"(gptr) : "memory");
}
__device__ __forceinline__ void cp_commit() {
    asm volatile("cp.async.commit_group;" ::: "memory");
}
__device__ __forceinline__ void cp_wait1() {
    asm volatile("cp.async.wait_group 1;" ::: "memory");
}

// ---------------------------------------------------------------------------
// Prototype normalize + bf16 convert (1024 padded rows, zero tail).
// ---------------------------------------------------------------------------
__global__ void __launch_bounds__(256) conv_proto_kernel(const float* __restrict__ x) {
    int gw   = (blockIdx.x * blockDim.x + threadIdx.x) >> 5;
    int lane = threadIdx.x & 31;
    if (gw >= C_PAD) return;
    uint4 o4 = {0u, 0u, 0u, 0u};
    if (gw < C_COLS) {
        const float4* r4 = reinterpret_cast<const float4*>(x + (size_t)gw * FDIM);
        float4 a = r4[lane * 2], b = r4[lane * 2 + 1];
        float s = a.x*a.x + a.y*a.y + a.z*a.z + a.w*a.w + b.x*b.x + b.y*b.y + b.z*b.z + b.w*b.w;
#pragma unroll
        for (int o = 16; o; o >>= 1) s += __shfl_xor_sync(0xffffffffu, s, o);
        float inv = 1.0f / fmaxf(sqrtf(s), 1e-12f);
        __nv_bfloat162 p0 = __floats2bfloat162_rn(a.x*inv, a.y*inv);
        __nv_bfloat162 p1 = __floats2bfloat162_rn(a.z*inv, a.w*inv);
        __nv_bfloat162 p2 = __floats2bfloat162_rn(b.x*inv, b.y*inv);
        __nv_bfloat162 p3 = __floats2bfloat162_rn(b.z*inv, b.w*inv);
        o4.x = *reinterpret_cast<uint32_t*>(&p0); o4.y = *reinterpret_cast<uint32_t*>(&p1);
        o4.z = *reinterpret_cast<uint32_t*>(&p2); o4.w = *reinterpret_cast<uint32_t*>(&p3);
    }
    reinterpret_cast<uint4*>(g_pb)[(size_t)gw * 32 + lane] = o4;
}

// ---------------------------------------------------------------------------
// Fused single-pass: normalize A -> HMMA GEMM with register-resident 32x1024
// cos tile -> iso in regs -> rowmean -> final logits stored once.
// 8 warps, each owns a 16-col slice per 128-col chunk (warp tile 32x16).
// ---------------------------------------------------------------------------
__global__ void __launch_bounds__(256, 1) fused_kernel(
    const float* __restrict__ feats,
    const float* __restrict__ dscale,
    const float* __restrict__ temp,
    float* __restrict__ out)
{
    extern __shared__ char smem[];
    char*  smA = smem;
    char*  smB = smem + A_BYTES;
    float* rs  = reinterpret_cast<float*>(smem + RS_OFF);

    const uint32_t sbA  = smem_u32(smA);
    const uint32_t sbB  = smem_u32(smB);

    const int tid  = threadIdx.x;
    const int wid  = tid >> 5;
    const int lane = tid & 31;
    const int q    = lane >> 2;        // row-within-8 of fragments
    const int row0 = blockIdx.x * TM;

    if (tid < TM) rs[tid] = 0.0f;

    // ---- B chunk loader: 128 rows x 32 16B-chunks = 16 cp.async per thread ----
    const char* pbB = reinterpret_cast<const char*>(g_pb);
    auto load_chunk = [&](int nc, int buf) {
#pragma unroll
        for (int i = 0; i < 16; i++) {
            int idx = tid + i * 256;
            int r = idx >> 5, kc = idx & 31;
            cp_async16(sbB + buf * B_BUF + r * ROWB + kc * 16,
                       pbB + ((size_t)(nc * TNC + r) * FDIM + kc * 8) * 2);
        }
        cp_commit();
    };

    // prologue: prefetch chunks 0 and 1 (overlaps with A normalize below)
    load_chunk(0, 0);
    load_chunk(1, 1);

    // ---- A tile: load fp32, normalize, convert, store bf16 (warp per row) ----
    const float4* f4 = reinterpret_cast<const float4*>(feats);
#pragma unroll
    for (int rr = 0; rr < TM / 8; rr++) {
        int r = wid + rr * 8;
        float4 a = f4[(size_t)(row0 + r) * 64 + lane * 2];
        float4 b = f4[(size_t)(row0 + r) * 64 + lane * 2 + 1];
        float sn = a.x*a.x + a.y*a.y + a.z*a.z + a.w*a.w + b.x*b.x + b.y*b.y + b.z*b.z + b.w*b.w;
#pragma unroll
        for (int o = 16; o; o >>= 1) sn += __shfl_xor_sync(0xffffffffu, sn, o);
        float inv = 1.0f / fmaxf(sqrtf(sn), 1e-12f);
        __nv_bfloat162 p0 = __floats2bfloat162_rn(a.x*inv, a.y*inv);
        __nv_bfloat162 p1 = __floats2bfloat162_rn(a.z*inv, a.w*inv);
        __nv_bfloat162 p2 = __floats2bfloat162_rn(b.x*inv, b.y*inv);
        __nv_bfloat162 p3 = __floats2bfloat162_rn(b.z*inv, b.w*inv);
        uint4 o4;
        o4.x = *reinterpret_cast<uint32_t*>(&p0); o4.y = *reinterpret_cast<uint32_t*>(&p1);
        o4.z = *reinterpret_cast<uint32_t*>(&p2); o4.w = *reinterpret_cast<uint32_t*>(&p3);
        *reinterpret_cast<uint4*>(smA + r * ROWB + lane * 16) = o4;
    }

    const uint32_t aBase = sbA + (uint32_t)((lane & 15) * APAD + ((lane >> 4) << 3)) * 2;
    const uint32_t bOff  = (uint32_t)((wid * 16 + (lane & 15)) * APAD + ((lane >> 4) << 3)) * 2;

    // ---- persistent cos accumulators: 8 chunks x (2m x 2n x 4) = 128 regs ----
    float acc[NCHUNKS][2][2][4];
#pragma unroll
    for (int nc = 0; nc < NCHUNKS; nc++)
#pragma unroll
        for (int i = 0; i < 2; i++)
#pragma unroll
            for (int j = 0; j < 2; j++)
#pragma unroll
                for (int c = 0; c < 4; c++) acc[nc][i][j][c] = 0.0f;

#pragma unroll
    for (int nc = 0; nc < NCHUNKS; nc++) {
        cp_wait1();
        __syncthreads();     // chunk nc visible (also orders A tile on nc==0)

        const uint32_t bBase = sbB + (nc & 1) * B_BUF + bOff;

#pragma unroll
        for (int k0 = 0; k0 < FDIM; k0 += 16) {
            uint32_t a0[4], a1[4], b[4];
            ldsm4(a0, aBase + k0 * 2);
            ldsm4(a1, aBase + 16 * ROWB + k0 * 2);
            ldsm4(b,  bBase + k0 * 2);
            mma16816(acc[nc][0][0], a0, b[0], b[2]);
            mma16816(acc[nc][0][1], a0, b[1], b[3]);
            mma16816(acc[nc][1][0], a1, b[0], b[2]);
            mma16816(acc[nc][1][1], a1, b[1], b[3]);
        }
        __syncthreads();     // buffer reads done before refill

        if (nc + 2 < NCHUNKS) load_chunk(nc + 2, nc & 1);
        else                  cp_commit();     // keep group count invariant
    }

    // ---- iso in place + per-row partial sums ----
    const float s = fabsf(__ldg(dscale));
    float rsum[4] = {0.f, 0.f, 0.f, 0.f};
#pragma unroll
    for (int nc = 0; nc < NCHUNKS; nc++) {
        int cbase = nc * TNC + wid * 16 + (lane & 3) * 2;
#pragma unroll
        for (int i = 0; i < 2; i++)
#pragma unroll
            for (int j = 0; j < 2; j++) {
                int col = cbase + 8 * j;
                if (col < C_COLS) {
                    float* a = acc[nc][i][j];
                    a[0] = s * sqrtf(fmaxf(1.0f - a[0], 0.0f));
                    a[1] = s * sqrtf(fmaxf(1.0f - a[1], 0.0f));
                    a[2] = s * sqrtf(fmaxf(1.0f - a[2], 0.0f));
                    a[3] = s * sqrtf(fmaxf(1.0f - a[3], 0.0f));
                    rsum[2 * i]     += a[0] + a[1];
                    rsum[2 * i + 1] += a[2] + a[3];
                }
            }
    }

    // reduce over the 4 lanes sharing each row, then 8 warps via smem atomics
#pragma unroll
    for (int k = 0; k < 4; k++) {
        float v = rsum[k];
        v += __shfl_xor_sync(0xffffffffu, v, 1);
        v += __shfl_xor_sync(0xffffffffu, v, 2);
        if ((lane & 3) == 0) atomicAdd(&rs[q + 8 * k], v);
    }
    __syncthreads();

    // ---- final store: logits = -(iso + mean)/T, straight from registers ----
    const float itT = 1.0f / __ldg(temp);
    float mean[4];
#pragma unroll
    for (int k = 0; k < 4; k++) mean[k] = rs[q + 8 * k] * (1.0f / (float)C_COLS);

#pragma unroll
    for (int nc = 0; nc < NCHUNKS; nc++) {
        int cbase = nc * TNC + wid * 16 + (lane & 3) * 2;
#pragma unroll
        for (int i = 0; i < 2; i++) {
            int r0 = row0 + 16 * i + q;
#pragma unroll
            for (int j = 0; j < 2; j++) {
                int col = cbase + 8 * j;
                if (col < C_COLS) {
                    const float* a = acc[nc][i][j];
                    float2 v0 = make_float2(-(a[0] + mean[2*i])     * itT,
                                            -(a[1] + mean[2*i])     * itT);
                    float2 v1 = make_float2(-(a[2] + mean[2*i + 1]) * itT,
                                            -(a[3] + mean[2*i + 1]) * itT);
                    *reinterpret_cast<float2*>(&out[(size_t)r0 * C_COLS + col])       = v0;
                    *reinterpret_cast<float2*>(&out[(size_t)(r0 + 8) * C_COLS + col]) = v1;
                }
            }
        }
    }
}

// ---------------------------------------------------------------------------
extern "C" void kernel_launch(void* const* d_in, const int* in_sizes, int n_in,
                              void* d_out, int out_size)
{
    const float* feats  = (const float*)d_in[0];
    const float* protos = (const float*)d_in[1];
    const float* ds     = (const float*)d_in[2];
    const float* temp   = (const float*)d_in[3];
    float* out = (float*)d_out;

    cudaFuncSetAttribute(fused_kernel,
                         cudaFuncAttributeMaxDynamicSharedMemorySize, SMEM_TOTAL);

    conv_proto_kernel<<<C_PAD / 8, 256>>>(protos);
    fused_kernel<<<B_ROWS / TM, 256, SMEM_TOTAL>>>(feats, ds, temp, out);
}